// round 4
// baseline (speedup 1.0000x reference)
#include <cuda_runtime.h>
#include <math.h>

#define GN 20000
#define GE 320000
#define NCHUNK 20   // ceil(GN / 1024)
// C=64, F=128, NUM_REL=2

// ---------------- scratch (static device globals; no runtime alloc) ----------
__device__ float g_W0[128 * 384];
__device__ float g_B0[384];
__device__ float g_W1[64 * 384];
__device__ float g_B1[384];
__device__ float g_OUT0[(size_t)GN * 384]; // layer0: [hp | mp0 | mp1 | he | me0 | me1]
__device__ float g_OUT1[(size_t)GN * 384]; // layer1: same layout
__device__ float g_P[(size_t)GN * 64];     // log_softmax(s)
__device__ float g_XE[(size_t)GN * 64];    // relu'd g1e output
__device__ float g_CO[64 * 192];           // P^T @ [M0 | M1 | XE]  = [A0 | A1 | x1]

// CSR scratch
__device__ int   g_deg[2][GN];
__device__ int   g_off[2][GN + 1];
__device__ int   g_cur[2][GN];
__device__ int   g_csum[2][NCHUNK];
__device__ int   g_esrc[2][GE];
__device__ float g_eattr[2][GE];

// ---------------- weight packing --------------------------------------------
__global__ void pack_weights(const float* __restrict__ pws0, const float* __restrict__ pwr0,
                             const float* __restrict__ pws1, const float* __restrict__ pwr1,
                             const float* __restrict__ pb,
                             const float* __restrict__ ews0, const float* __restrict__ ewr0,
                             const float* __restrict__ ews1, const float* __restrict__ ewr1,
                             const float* __restrict__ eb)
{
    int i = blockIdx.x * 256 + threadIdx.x;
    if (i < 128 * 384) {
        int k = i / 384, j = i % 384;
        int g = j >> 6, c = j & 63;
        float v;
        switch (g) {
            case 0: v = pws0[k * 64 + c]; break;
            case 1: v = pwr0[k * 64 + c]; break;
            case 2: v = pwr0[8192 + k * 64 + c]; break;
            case 3: v = ews0[k * 64 + c]; break;
            case 4: v = ewr0[k * 64 + c]; break;
            default: v = ewr0[8192 + k * 64 + c]; break;
        }
        g_W0[i] = v;
    }
    if (i < 64 * 384) {
        int k = i / 384, j = i % 384;
        int g = j >> 6, c = j & 63;
        float v;
        switch (g) {
            case 0: v = pws1[k * 64 + c]; break;
            case 1: v = pwr1[k * 64 + c]; break;
            case 2: v = pwr1[4096 + k * 64 + c]; break;
            case 3: v = ews1[k * 64 + c]; break;
            case 4: v = ewr1[k * 64 + c]; break;
            default: v = ewr1[4096 + k * 64 + c]; break;
        }
        g_W1[i] = v;
    }
    if (i < 384) {
        int g = i >> 6, c = i & 63;
        g_B0[i] = (g == 0) ? pb[c] : (g == 3 ? eb[c] : 0.f);
        g_B1[i] = (g == 0) ? pb[64 + c] : (g == 3 ? eb[64 + c] : 0.f);
    }
}

// ---------------- zero small scratch (degree counters + g_CO) ----------------
__global__ void zero_small()
{
    int i = blockIdx.x * 256 + threadIdx.x;
    if (i < 2 * GN) ((int*)g_deg)[i] = 0;
    else if (i < 2 * GN + 64 * 192) g_CO[i - 2 * GN] = 0.f;
}

// ---------------- CSR build: histogram -> chunk scan -> fixup -> place -------
__global__ void hist_kernel(const int* __restrict__ e0, const int* __restrict__ e1)
{
    int i = blockIdx.x * 256 + threadIdx.x;
    if (i < GE) atomicAdd(&g_deg[0][e0[i]], 1);
    else if (i < 2 * GE) atomicAdd(&g_deg[1][e1[i - GE]], 1);
}

// chunk-local exclusive scan via warp shuffles; grid = 2 * NCHUNK blocks x 1024
__global__ void scan_chunks()
{
    int b = blockIdx.x;
    int r = b / NCHUNK, ch = b % NCHUNK;
    int t = threadIdx.x;
    int i = ch * 1024 + t;
    int lane = t & 31, wid = t >> 5;
    int v = (i < GN) ? g_deg[r][i] : 0;
    int inc = v;
#pragma unroll
    for (int o = 1; o < 32; o <<= 1) {
        int u = __shfl_up_sync(0xffffffffu, inc, o);
        if (lane >= o) inc += u;
    }
    __shared__ int wt[32];
    if (lane == 31) wt[wid] = inc;
    __syncthreads();
    if (wid == 0) {
        int wv = wt[lane];
        int winc = wv;
#pragma unroll
        for (int o = 1; o < 32; o <<= 1) {
            int u = __shfl_up_sync(0xffffffffu, winc, o);
            if (lane >= o) winc += u;
        }
        wt[lane] = winc - wv; // exclusive warp offset
    }
    __syncthreads();
    int excl = inc - v + wt[wid];
    if (i < GN) g_off[r][i] = excl;
    if (t == 1023) g_csum[r][ch] = excl + v; // chunk total
}

// add chunk prefix; grid = 2 * NCHUNK blocks x 1024
__global__ void scan_fixup()
{
    int b = blockIdx.x;
    int r = b / NCHUNK, ch = b % NCHUNK;
    int t = threadIdx.x;
    int i = ch * 1024 + t;
    __shared__ int pre;
    if (t == 0) {
        int s = 0;
        for (int k = 0; k < ch; k++) s += g_csum[r][k];
        pre = s;
        if (ch == NCHUNK - 1) g_off[r][GN] = s + g_csum[r][ch];
    }
    __syncthreads();
    if (i < GN) {
        int o = g_off[r][i] + pre;
        g_off[r][i] = o;
        g_cur[r][i] = o;
    }
}

__global__ void place_kernel(const int* __restrict__ e0, const float* __restrict__ a0,
                             const int* __restrict__ e1, const float* __restrict__ a1)
{
    int i = blockIdx.x * 256 + threadIdx.x;
    int r, j;
    const int* e;
    const float* at;
    if (i < GE) { r = 0; j = i; e = e0; at = a0; }
    else if (i < 2 * GE) { r = 1; j = i - GE; e = e1; at = a1; }
    else return;
    int dst = e[j];
    int src = e[GE + j];
    float a = at[j];
    int pos = atomicAdd(&g_cur[r][dst], 1);
    g_esrc[r][pos] = src;
    g_eattr[r][pos] = a;
}

// ---------------- big GEMM (M x K @ K x 384) --------------------------------
__device__ __forceinline__ void gemm_body(const float* __restrict__ A, int lda, int aGroupStride,
                                          const float* __restrict__ W, const float* __restrict__ bias,
                                          float* __restrict__ C, int K)
{
    __shared__ float As[64][36];
    __shared__ float Bs[32][64];
    int tid = threadIdx.x;
    int m0 = blockIdx.x * 64;
    int n0 = blockIdx.y * 64;
    const float* Ab = A + (n0 / 192) * aGroupStride;
    int tx = tid & 15, ty = tid >> 4;
    float acc[4][4] = {};
    for (int kk = 0; kk < K; kk += 32) {
#pragma unroll
        for (int l = 0; l < 2; l++) {
            int f = tid + l * 256;
            int r = f >> 3, c4 = (f & 7) << 2;
            int gm = m0 + r;
            float4 v = make_float4(0.f, 0.f, 0.f, 0.f);
            if (gm < GN) v = *(const float4*)(Ab + (size_t)gm * lda + kk + c4);
            *(float4*)&As[r][c4] = v;
        }
#pragma unroll
        for (int l = 0; l < 2; l++) {
            int f = tid + l * 256;
            int r = f >> 4, c4 = (f & 15) << 2;
            *(float4*)&Bs[r][c4] = *(const float4*)(W + (size_t)(kk + r) * 384 + n0 + c4);
        }
        __syncthreads();
#pragma unroll
        for (int k = 0; k < 32; k++) {
            float a0 = As[ty * 4 + 0][k];
            float a1 = As[ty * 4 + 1][k];
            float a2 = As[ty * 4 + 2][k];
            float a3 = As[ty * 4 + 3][k];
            float4 bv = *(float4*)&Bs[k][tx * 4];
            acc[0][0] += a0 * bv.x; acc[0][1] += a0 * bv.y; acc[0][2] += a0 * bv.z; acc[0][3] += a0 * bv.w;
            acc[1][0] += a1 * bv.x; acc[1][1] += a1 * bv.y; acc[1][2] += a1 * bv.z; acc[1][3] += a1 * bv.w;
            acc[2][0] += a2 * bv.x; acc[2][1] += a2 * bv.y; acc[2][2] += a2 * bv.z; acc[2][3] += a2 * bv.w;
            acc[3][0] += a3 * bv.x; acc[3][1] += a3 * bv.y; acc[3][2] += a3 * bv.z; acc[3][3] += a3 * bv.w;
        }
        __syncthreads();
    }
#pragma unroll
    for (int i = 0; i < 4; i++) {
        int gm = m0 + ty * 4 + i;
        if (gm >= GN) continue;
#pragma unroll
        for (int j = 0; j < 4; j++)
            C[(size_t)gm * 384 + n0 + tx * 4 + j] = acc[i][j] + bias[n0 + tx * 4 + j];
    }
}

__global__ void gemm0_kernel(const float* __restrict__ x) { gemm_body(x, 128, 0, g_W0, g_B0, g_OUT0, 128); }
__global__ void gemm1_kernel() { gemm_body(g_OUT0, 384, 192, g_W1, g_B1, g_OUT1, 64); }

// ---------------- gather (segment sum via CSR), one warp per node ------------
// LAYER 0: h = relu(h_self + sum), written back in place (cols 0:64, 192:256)
// LAYER 1: fused finalize: s -> dout, xe -> g_XE, log_softmax(s) -> g_P
template <int LAYER>
__global__ void gather_layer(float* __restrict__ dout, int full)
{
    int node = blockIdx.x * 8 + (threadIdx.x >> 5);
    if (node >= GN) return;
    int lane = threadIdx.x & 31;
    float* buf = LAYER ? g_OUT1 : g_OUT0;
    float2 accp = make_float2(0.f, 0.f);
    float2 acce = make_float2(0.f, 0.f);
#pragma unroll
    for (int r = 0; r < 2; r++) {
        int beg = g_off[r][node], end = g_off[r][node + 1];
        const int* __restrict__ es = g_esrc[r];
        const float* __restrict__ ea = g_eattr[r];
        for (int k = beg; k < end; k++) {
            int src = es[k];
            float a = ea[k];
            const float* rp = buf + (size_t)src * 384;
            float2 mp = *(const float2*)(rp + 64 + r * 64 + lane * 2);
            float2 me = *(const float2*)(rp + 256 + r * 64 + lane * 2);
            accp.x += a * mp.x; accp.y += a * mp.y;
            acce.x += a * me.x; acce.y += a * me.y;
        }
    }
    float* wp = buf + (size_t)node * 384;
    float2 hp = *(const float2*)(wp + lane * 2);
    float2 he = *(const float2*)(wp + 192 + lane * 2);
    hp.x = fmaxf(hp.x + accp.x, 0.f);
    hp.y = fmaxf(hp.y + accp.y, 0.f);
    he.x = fmaxf(he.x + acce.x, 0.f);
    he.y = fmaxf(he.y + acce.y, 0.f);
    if (LAYER == 0) {
        *(float2*)(wp + lane * 2) = hp;
        *(float2*)(wp + 192 + lane * 2) = he;
    } else {
        if (full) *(float2*)(dout + 32 + (size_t)node * 64 + lane * 2) = hp;
        *(float2*)(g_XE + (size_t)node * 64 + lane * 2) = he;
        float m = fmaxf(hp.x, hp.y);
#pragma unroll
        for (int off = 16; off; off >>= 1) m = fmaxf(m, __shfl_xor_sync(0xffffffffu, m, off));
        float sum = expf(hp.x - m) + expf(hp.y - m);
#pragma unroll
        for (int off = 16; off; off >>= 1) sum += __shfl_xor_sync(0xffffffffu, sum, off);
        float lse = m + logf(sum);
        *(float2*)(g_P + (size_t)node * 64 + lane * 2) = make_float2(hp.x - lse, hp.y - lse);
    }
}

// ---------------- fused coarsen + P^T @ [M0 | M1 | XE]  -> g_CO [64 x 192] ---
// Per 8-node chunk: warp w gathers M rows for node n0+w directly into smem
// (M_r[n] = sum a * P[src]), loads P and XE rows, then the block accumulates
// the 64x192 outer product. g_M buffer eliminated.
#define PT_NB 8
__global__ void ptgemm_kernel()
{
    __shared__ float Ps[PT_NB][64];
    __shared__ float Bsr[PT_NB][192];
    int tid = threadIdx.x;
    int lane = tid & 31;
    int w = tid >> 5;   // 8 warps
    int ag = tid & 15;  // a-rows ag*4 .. +3
    int bg = tid >> 4;  // b-cols bg*12 .. +11
    float acc[4][12] = {};
    int rpb = (GN + gridDim.x - 1) / gridDim.x;
    int r0 = blockIdx.x * rpb;
    int r1 = min(GN, r0 + rpb);
    for (int n0 = r0; n0 < r1; n0 += PT_NB) {
        __syncthreads();
        int n = n0 + w;
        if (n < r1) {
            float2 p = *(const float2*)(g_P + (size_t)n * 64 + lane * 2);
            Ps[w][lane * 2] = p.x;
            Ps[w][lane * 2 + 1] = p.y;
            float2 xe = *(const float2*)(g_XE + (size_t)n * 64 + lane * 2);
            Bsr[w][128 + lane * 2] = xe.x;
            Bsr[w][129 + lane * 2] = xe.y;
            float2 m0v = make_float2(0.f, 0.f);
            float2 m1v = make_float2(0.f, 0.f);
#pragma unroll
            for (int r = 0; r < 2; r++) {
                int beg = g_off[r][n], end = g_off[r][n + 1];
                const int* __restrict__ es = g_esrc[r];
                const float* __restrict__ ea = g_eattr[r];
                for (int k = beg; k < end; k++) {
                    int src = es[k];
                    float a = ea[k];
                    float2 pv = *(const float2*)(g_P + (size_t)src * 64 + lane * 2);
                    if (r == 0) { m0v.x += a * pv.x; m0v.y += a * pv.y; }
                    else        { m1v.x += a * pv.x; m1v.y += a * pv.y; }
                }
            }
            Bsr[w][lane * 2] = m0v.x;
            Bsr[w][lane * 2 + 1] = m0v.y;
            Bsr[w][64 + lane * 2] = m1v.x;
            Bsr[w][65 + lane * 2] = m1v.y;
        } else {
#pragma unroll
            for (int q = 0; q < 2; q++) {
                Ps[w][lane * 2 + q] = 0.f;
                Bsr[w][lane * 2 + q] = 0.f;
                Bsr[w][64 + lane * 2 + q] = 0.f;
                Bsr[w][128 + lane * 2 + q] = 0.f;
            }
        }
        __syncthreads();
#pragma unroll
        for (int j = 0; j < PT_NB; j++) {
            float a[4];
#pragma unroll
            for (int i = 0; i < 4; i++) a[i] = Ps[j][ag * 4 + i];
            float b[12];
#pragma unroll
            for (int q = 0; q < 12; q++) b[q] = Bsr[j][bg * 12 + q];
#pragma unroll
            for (int i = 0; i < 4; i++)
#pragma unroll
                for (int q = 0; q < 12; q++) acc[i][q] += a[i] * b[q];
        }
    }
#pragma unroll
    for (int i = 0; i < 4; i++)
#pragma unroll
        for (int q = 0; q < 12; q++)
            atomicAdd(&g_CO[(ag * 4 + i) * 192 + bg * 12 + q], acc[i][q]);
}

// ---------------- dense 64x64 GNN + head ------------------------------------
#define DSTR 68

template <bool ACC, bool BSMEM>
__device__ __forceinline__ void dmm(float* Cs, const float* As, const float* B,
                                    const float* bias, int tid)
{
    int r0 = (tid >> 4) << 2, c0 = (tid & 15) << 2;
    float acc[4][4];
#pragma unroll
    for (int i = 0; i < 4; i++)
#pragma unroll
        for (int j = 0; j < 4; j++)
            acc[i][j] = ACC ? Cs[(r0 + i) * DSTR + c0 + j] : (bias ? bias[c0 + j] : 0.f);
#pragma unroll 8
    for (int k = 0; k < 64; k++) {
        float a[4];
#pragma unroll
        for (int i = 0; i < 4; i++) a[i] = As[(r0 + i) * DSTR + k];
        float4 bv;
        if (BSMEM) bv = *(const float4*)(B + k * DSTR + c0);
        else bv = *(const float4*)(B + k * 64 + c0);
#pragma unroll
        for (int i = 0; i < 4; i++) {
            acc[i][0] += a[i] * bv.x;
            acc[i][1] += a[i] * bv.y;
            acc[i][2] += a[i] * bv.z;
            acc[i][3] += a[i] * bv.w;
        }
    }
#pragma unroll
    for (int i = 0; i < 4; i++)
#pragma unroll
        for (int j = 0; j < 4; j++)
            Cs[(r0 + i) * DSTR + c0 + j] = acc[i][j];
}

__global__ void dense_final(const float* __restrict__ Wself0, const float* __restrict__ Wrel0,
                            const float* __restrict__ Wself1, const float* __restrict__ Wrel1,
                            const float* __restrict__ gb,
                            const float* __restrict__ lin1W, const float* __restrict__ lin1b,
                            const float* __restrict__ lin2W, const float* __restrict__ lin2b,
                            float* __restrict__ dout, int full)
{
    extern __shared__ float sm[];
    float* X = sm;
    float* A0 = X + 64 * DSTR;
    float* A1 = A0 + 64 * DSTR;
    float* H = A1 + 64 * DSTR;
    float* H2 = H + 64 * DSTR;
    float* T = H2 + 64 * DSTR;
    int tid = threadIdx.x;
    int r0 = (tid >> 4) << 2, c0 = (tid & 15) << 2;
#pragma unroll
    for (int i = 0; i < 4; i++)
#pragma unroll
        for (int j = 0; j < 4; j++) {
            int r = r0 + i, c = c0 + j;
            float xv = g_CO[r * 192 + 128 + c];
            X[r * DSTR + c] = xv;
            if (full) dout[32 + (size_t)GN * 64 + r * 64 + c] = xv;
            A0[r * DSTR + c] = g_CO[r * 192 + c];
            A1[r * DSTR + c] = g_CO[r * 192 + 64 + c];
        }
    __syncthreads();
    dmm<false, false>(H, X, Wself0, gb, tid);          // H = X@Ws0 + b0
    dmm<false, false>(T, X, Wrel0, nullptr, tid);      // T = X@Wr0[0]
    __syncthreads();
    dmm<true, true>(H, A0, T, nullptr, tid);           // H += A0@T
    __syncthreads();
    dmm<false, false>(T, X, Wrel0 + 4096, nullptr, tid);
    __syncthreads();
    dmm<true, true>(H, A1, T, nullptr, tid);
#pragma unroll
    for (int i = 0; i < 4; i++)
#pragma unroll
        for (int j = 0; j < 4; j++) {
            float* p = &H[(r0 + i) * DSTR + c0 + j];
            *p = fmaxf(*p, 0.f);
        }
    __syncthreads();
    dmm<false, false>(H2, H, Wself1, gb + 64, tid);    // H2 = H@Ws1 + b1
    dmm<false, false>(T, H, Wrel1, nullptr, tid);
    __syncthreads();
    dmm<true, true>(H2, A0, T, nullptr, tid);
    __syncthreads();
    dmm<false, false>(T, H, Wrel1 + 4096, nullptr, tid);
    __syncthreads();
    dmm<true, true>(H2, A1, T, nullptr, tid);
#pragma unroll
    for (int i = 0; i < 4; i++)
#pragma unroll
        for (int j = 0; j < 4; j++) {
            float* p = &H2[(r0 + i) * DSTR + c0 + j];
            *p = fmaxf(*p, 0.f);
        }
    __syncthreads();
    if (tid < 64) {
        float s = 0.f;
        for (int r = 0; r < 64; r++) s += H2[r * DSTR + tid];
        T[tid] = s * (1.f / 64.f); // pooled mean over rows
    }
    __syncthreads();
    if (tid < 32) {
        float h1 = lin1b[tid];
        for (int c = 0; c < 64; c++) h1 += T[c] * lin1W[c * 32 + tid];
        h1 = (h1 > 0.f) ? h1 : 0.01f * h1; // leaky_relu
        T[64 + tid] = h1;
        __syncwarp();
        float lg = lin2b[tid];
        for (int j = 0; j < 32; j++) lg += T[64 + j] * lin2W[j * 32 + tid];
        float m = lg;
#pragma unroll
        for (int off = 16; off; off >>= 1) m = fmaxf(m, __shfl_xor_sync(0xffffffffu, m, off));
        float se = expf(lg - m);
#pragma unroll
        for (int off = 16; off; off >>= 1) se += __shfl_xor_sync(0xffffffffu, se, off);
        dout[tid] = lg - m - logf(se);
    }
}

// ---------------- launcher ---------------------------------------------------
extern "C" void kernel_launch(void* const* d_in, const int* in_sizes, int n_in,
                              void* d_out, int out_size)
{
    const float* x = (const float*)d_in[0];
    // resolve edge/attr ordering by sizes (dict order vs signature order)
    int iE0 = 1, iA0 = 2, iE1 = 3, iA1 = 4;
    if (in_sizes[2] == 2 * GE) { iE0 = 1; iE1 = 2; iA0 = 3; iA1 = 4; }
    const int* e0 = (const int*)d_in[iE0];
    const float* a0 = (const float*)d_in[iA0];
    const int* e1 = (const int*)d_in[iE1];
    const float* a1 = (const float*)d_in[iA1];
    const float* W[19];
    for (int i = 0; i < 19; i++) W[i] = (const float*)d_in[5 + i];
    int full = (out_size >= 32 + GN * 64 + 64 * 64) ? 1 : 0;
    float* dout = (float*)d_out;

    cudaFuncSetAttribute(dense_final, cudaFuncAttributeMaxDynamicSharedMemorySize,
                         6 * 64 * DSTR * (int)sizeof(float));

    pack_weights<<<192, 256>>>(W[0], W[1], W[2], W[3], W[4], W[5], W[6], W[7], W[8], W[9]);
    zero_small<<<205, 256>>>();
    hist_kernel<<<2500, 256>>>(e0, e1);
    scan_chunks<<<2 * NCHUNK, 1024>>>();
    scan_fixup<<<2 * NCHUNK, 1024>>>();
    place_kernel<<<2500, 256>>>(e0, a0, e1, a1);
    gemm0_kernel<<<dim3(313, 6), 256>>>(x);
    gather_layer<0><<<2500, 256>>>(dout, full);
    gemm1_kernel<<<dim3(313, 6), 256>>>();
    gather_layer<1><<<2500, 256>>>(dout, full);
    ptgemm_kernel<<<160, 256>>>();
    dense_final<<<1, 256, 6 * 64 * DSTR * sizeof(float)>>>(
        W[10], W[11], W[12], W[13], W[14], W[15], W[16], W[17], W[18], dout, full);
}

// round 9
// speedup vs baseline: 1.0331x; 1.0331x over previous
#include <cuda_runtime.h>
#include <math.h>

#define GN 20000
#define GE 320000
#define NCHUNK 20   // ceil(GN / 1024)
// C=64, F=128, NUM_REL=2

// ---------------- scratch (static device globals; no runtime alloc) ----------
__device__ float g_W0[128 * 384];
__device__ float g_B0[384];
__device__ float g_W1[64 * 384];
__device__ float g_B1[384];
__device__ float g_OUT0[(size_t)GN * 384]; // layer0: [hp | mp0 | mp1 | he | me0 | me1]
__device__ float g_OUT1[(size_t)GN * 384]; // layer1: same layout
__device__ float g_P[(size_t)GN * 64];     // log_softmax(s)
__device__ float g_XE[(size_t)GN * 64];    // relu'd g1e output
__device__ float g_CO[64 * 192];           // P^T @ [M0 | M1 | XE]  = [A0 | A1 | x1]

// CSR scratch
__device__ int   g_deg[2][GN];
__device__ int   g_off[2][GN + 1];
__device__ int   g_cur[2][GN];
__device__ int   g_csum[2][NCHUNK];
__device__ int   g_esrc[2][GE];
__device__ float g_eattr[2][GE];

// ---------------- weight packing --------------------------------------------
__global__ void pack_weights(const float* __restrict__ pws0, const float* __restrict__ pwr0,
                             const float* __restrict__ pws1, const float* __restrict__ pwr1,
                             const float* __restrict__ pb,
                             const float* __restrict__ ews0, const float* __restrict__ ewr0,
                             const float* __restrict__ ews1, const float* __restrict__ ewr1,
                             const float* __restrict__ eb)
{
    int i = blockIdx.x * 256 + threadIdx.x;
    if (i < 128 * 384) {
        int k = i / 384, j = i % 384;
        int g = j >> 6, c = j & 63;
        float v;
        switch (g) {
            case 0: v = pws0[k * 64 + c]; break;
            case 1: v = pwr0[k * 64 + c]; break;
            case 2: v = pwr0[8192 + k * 64 + c]; break;
            case 3: v = ews0[k * 64 + c]; break;
            case 4: v = ewr0[k * 64 + c]; break;
            default: v = ewr0[8192 + k * 64 + c]; break;
        }
        g_W0[i] = v;
    }
    if (i < 64 * 384) {
        int k = i / 384, j = i % 384;
        int g = j >> 6, c = j & 63;
        float v;
        switch (g) {
            case 0: v = pws1[k * 64 + c]; break;
            case 1: v = pwr1[k * 64 + c]; break;
            case 2: v = pwr1[4096 + k * 64 + c]; break;
            case 3: v = ews1[k * 64 + c]; break;
            case 4: v = ewr1[k * 64 + c]; break;
            default: v = ewr1[4096 + k * 64 + c]; break;
        }
        g_W1[i] = v;
    }
    if (i < 384) {
        int g = i >> 6, c = i & 63;
        g_B0[i] = (g == 0) ? pb[c] : (g == 3 ? eb[c] : 0.f);
        g_B1[i] = (g == 0) ? pb[64 + c] : (g == 3 ? eb[64 + c] : 0.f);
    }
}

// ---------------- zero small scratch (degree counters + g_CO) ----------------
__global__ void zero_small()
{
    int i = blockIdx.x * 256 + threadIdx.x;
    if (i < 2 * GN) ((int*)g_deg)[i] = 0;
    else if (i < 2 * GN + 64 * 192) g_CO[i - 2 * GN] = 0.f;
}

// ---------------- CSR build: histogram -> chunk scan -> fixup -> place -------
__global__ void hist_kernel(const int* __restrict__ e0, const int* __restrict__ e1)
{
    int i = blockIdx.x * 256 + threadIdx.x;
    if (i < GE) atomicAdd(&g_deg[0][e0[i]], 1);
    else if (i < 2 * GE) atomicAdd(&g_deg[1][e1[i - GE]], 1);
}

// chunk-local exclusive scan via warp shuffles; grid = 2 * NCHUNK blocks x 1024
__global__ void scan_chunks()
{
    int b = blockIdx.x;
    int r = b / NCHUNK, ch = b % NCHUNK;
    int t = threadIdx.x;
    int i = ch * 1024 + t;
    int lane = t & 31, wid = t >> 5;
    int v = (i < GN) ? g_deg[r][i] : 0;
    int inc = v;
#pragma unroll
    for (int o = 1; o < 32; o <<= 1) {
        int u = __shfl_up_sync(0xffffffffu, inc, o);
        if (lane >= o) inc += u;
    }
    __shared__ int wt[32];
    if (lane == 31) wt[wid] = inc;
    __syncthreads();
    if (wid == 0) {
        int wv = wt[lane];
        int winc = wv;
#pragma unroll
        for (int o = 1; o < 32; o <<= 1) {
            int u = __shfl_up_sync(0xffffffffu, winc, o);
            if (lane >= o) winc += u;
        }
        wt[lane] = winc - wv; // exclusive warp offset
    }
    __syncthreads();
    int excl = inc - v + wt[wid];
    if (i < GN) g_off[r][i] = excl;
    if (t == 1023) g_csum[r][ch] = excl + v; // chunk total
}

// add chunk prefix; grid = 2 * NCHUNK blocks x 1024
__global__ void scan_fixup()
{
    int b = blockIdx.x;
    int r = b / NCHUNK, ch = b % NCHUNK;
    int t = threadIdx.x;
    int i = ch * 1024 + t;
    __shared__ int pre;
    if (t == 0) {
        int s = 0;
        for (int k = 0; k < ch; k++) s += g_csum[r][k];
        pre = s;
        if (ch == NCHUNK - 1) g_off[r][GN] = s + g_csum[r][ch];
    }
    __syncthreads();
    if (i < GN) {
        int o = g_off[r][i] + pre;
        g_off[r][i] = o;
        g_cur[r][i] = o;
    }
}

__global__ void place_kernel(const int* __restrict__ e0, const float* __restrict__ a0,
                             const int* __restrict__ e1, const float* __restrict__ a1)
{
    int i = blockIdx.x * 256 + threadIdx.x;
    int r, j;
    const int* e;
    const float* at;
    if (i < GE) { r = 0; j = i; e = e0; at = a0; }
    else if (i < 2 * GE) { r = 1; j = i - GE; e = e1; at = a1; }
    else return;
    int dst = e[j];
    int src = e[GE + j];
    float a = at[j];
    int pos = atomicAdd(&g_cur[r][dst], 1);
    g_esrc[r][pos] = src;
    g_eattr[r][pos] = a;
}

// ---------------- SIMT fp32 GEMM (M x K @ K x 384), 128x64 tile --------------
// 256 threads; thread (tx = tid&15, ty = tid>>4) computes rows ty*8..+7,
// cols tx*4..+3. BK=16. A staged transposed As[k][m] (stride 132); inner loop
// = 3x LDS.128 + 32 FFMA per k. ALL global buffers bound in DEVICE code —
// never passed as host-side kernel args (that was the rounds-4..7 failure:
// host shadow addresses + ATS page migration => 128 MiB "allocation").
#define ASTR 132
__device__ __forceinline__ void gemm_simt_body(
    const float* __restrict__ A, int LDA, int GRPSTRIDE, int K,
    const float* __restrict__ W, const float* __restrict__ bias,
    float* __restrict__ Cout)
{
    __shared__ float As[16 * ASTR]; // [k][m], m stride 1
    __shared__ float Bs[16][64];    // [k][n]
    int tid = threadIdx.x;
    int tx = tid & 15;   // n group (4 cols)
    int ty = tid >> 4;   // m group (8 rows)
    int m0 = blockIdx.x * 128;
    int n0 = blockIdx.y * 64;
    const float* Ab = A + (n0 / 192) * GRPSTRIDE;

    float acc[8][4] = {};

    for (int kk = 0; kk < K; kk += 16) {
        // stage A: 128 rows x 16 k, transposed into As[k][m]
#pragma unroll
        for (int l = 0; l < 2; l++) {
            int f = tid + l * 256;          // 0..511
            int row = f >> 2;               // 0..127
            int kc = (f & 3) << 2;          // 0,4,8,12
            float4 v = make_float4(0.f, 0.f, 0.f, 0.f);
            if (m0 + row < GN) v = *(const float4*)(Ab + (size_t)(m0 + row) * LDA + kk + kc);
            As[(kc + 0) * ASTR + row] = v.x;
            As[(kc + 1) * ASTR + row] = v.y;
            As[(kc + 2) * ASTR + row] = v.z;
            As[(kc + 3) * ASTR + row] = v.w;
        }
        // stage B: 16 k x 64 n (1 float4 per thread)
        {
            int row = tid >> 4, c4 = (tid & 15) << 2;
            *(float4*)&Bs[row][c4] = *(const float4*)(W + (size_t)(kk + row) * 384 + n0 + c4);
        }
        __syncthreads();
#pragma unroll
        for (int k = 0; k < 16; k++) {
            float4 a0 = *(const float4*)&As[k * ASTR + ty * 8];
            float4 a1 = *(const float4*)&As[k * ASTR + ty * 8 + 4];
            float4 bv = *(const float4*)&Bs[k][tx * 4];
            acc[0][0] += a0.x * bv.x; acc[0][1] += a0.x * bv.y; acc[0][2] += a0.x * bv.z; acc[0][3] += a0.x * bv.w;
            acc[1][0] += a0.y * bv.x; acc[1][1] += a0.y * bv.y; acc[1][2] += a0.y * bv.z; acc[1][3] += a0.y * bv.w;
            acc[2][0] += a0.z * bv.x; acc[2][1] += a0.z * bv.y; acc[2][2] += a0.z * bv.z; acc[2][3] += a0.z * bv.w;
            acc[3][0] += a0.w * bv.x; acc[3][1] += a0.w * bv.y; acc[3][2] += a0.w * bv.z; acc[3][3] += a0.w * bv.w;
            acc[4][0] += a1.x * bv.x; acc[4][1] += a1.x * bv.y; acc[4][2] += a1.x * bv.z; acc[4][3] += a1.x * bv.w;
            acc[5][0] += a1.y * bv.x; acc[5][1] += a1.y * bv.y; acc[5][2] += a1.y * bv.z; acc[5][3] += a1.y * bv.w;
            acc[6][0] += a1.z * bv.x; acc[6][1] += a1.z * bv.y; acc[6][2] += a1.z * bv.z; acc[6][3] += a1.z * bv.w;
            acc[7][0] += a1.w * bv.x; acc[7][1] += a1.w * bv.y; acc[7][2] += a1.w * bv.z; acc[7][3] += a1.w * bv.w;
        }
        __syncthreads();
    }

    // epilogue: add bias, vector store
    float4 bv = *(const float4*)(bias + n0 + tx * 4);
#pragma unroll
    for (int i = 0; i < 8; i++) {
        int row = m0 + ty * 8 + i;
        if (row < GN) {
            float4 v = make_float4(acc[i][0] + bv.x, acc[i][1] + bv.y,
                                   acc[i][2] + bv.z, acc[i][3] + bv.w);
            *(float4*)(Cout + (size_t)row * 384 + n0 + tx * 4) = v;
        }
    }
}

// wrappers: only harness pointers cross the host/device boundary
__global__ void __launch_bounds__(256) gemm0_kernel(const float* __restrict__ x)
{
    gemm_simt_body(x, 128, 0, 128, g_W0, g_B0, g_OUT0);
}
__global__ void __launch_bounds__(256) gemm1_kernel()
{
    gemm_simt_body(g_OUT0, 384, 192, 64, g_W1, g_B1, g_OUT1);
}

// ---------------- gather (segment sum via CSR), one warp per node ------------
// LAYER 0: h = relu(h_self + sum), written back in place (cols 0:64, 192:256)
// LAYER 1: fused finalize: s -> dout, xe -> g_XE, log_softmax(s) -> g_P
template <int LAYER>
__global__ void gather_layer(float* __restrict__ dout, int full)
{
    int node = blockIdx.x * 8 + (threadIdx.x >> 5);
    if (node >= GN) return;
    int lane = threadIdx.x & 31;
    float* buf = LAYER ? g_OUT1 : g_OUT0;
    float2 accp = make_float2(0.f, 0.f);
    float2 acce = make_float2(0.f, 0.f);
#pragma unroll
    for (int r = 0; r < 2; r++) {
        int beg = g_off[r][node], end = g_off[r][node + 1];
        const int* __restrict__ es = g_esrc[r];
        const float* __restrict__ ea = g_eattr[r];
        for (int k = beg; k < end; k++) {
            int src = es[k];
            float a = ea[k];
            const float* rp = buf + (size_t)src * 384;
            float2 mp = *(const float2*)(rp + 64 + r * 64 + lane * 2);
            float2 me = *(const float2*)(rp + 256 + r * 64 + lane * 2);
            accp.x += a * mp.x; accp.y += a * mp.y;
            acce.x += a * me.x; acce.y += a * me.y;
        }
    }
    float* wp = buf + (size_t)node * 384;
    float2 hp = *(const float2*)(wp + lane * 2);
    float2 he = *(const float2*)(wp + 192 + lane * 2);
    hp.x = fmaxf(hp.x + accp.x, 0.f);
    hp.y = fmaxf(hp.y + accp.y, 0.f);
    he.x = fmaxf(he.x + acce.x, 0.f);
    he.y = fmaxf(he.y + acce.y, 0.f);
    if (LAYER == 0) {
        *(float2*)(wp + lane * 2) = hp;
        *(float2*)(wp + 192 + lane * 2) = he;
    } else {
        if (full) *(float2*)(dout + 32 + (size_t)node * 64 + lane * 2) = hp;
        *(float2*)(g_XE + (size_t)node * 64 + lane * 2) = he;
        float m = fmaxf(hp.x, hp.y);
#pragma unroll
        for (int off = 16; off; off >>= 1) m = fmaxf(m, __shfl_xor_sync(0xffffffffu, m, off));
        float sum = expf(hp.x - m) + expf(hp.y - m);
#pragma unroll
        for (int off = 16; off; off >>= 1) sum += __shfl_xor_sync(0xffffffffu, sum, off);
        float lse = m + logf(sum);
        *(float2*)(g_P + (size_t)node * 64 + lane * 2) = make_float2(hp.x - lse, hp.y - lse);
    }
}

// ---------------- fused coarsen + P^T @ [M0 | M1 | XE]  -> g_CO [64 x 192] ---
#define PT_NB 8
__global__ void ptgemm_kernel()
{
    __shared__ float Ps[PT_NB][64];
    __shared__ float Bsr[PT_NB][192];
    int tid = threadIdx.x;
    int lane = tid & 31;
    int w = tid >> 5;   // 8 warps
    int ag = tid & 15;  // a-rows ag*4 .. +3
    int bg = tid >> 4;  // b-cols bg*12 .. +11
    float acc[4][12] = {};
    int rpb = (GN + gridDim.x - 1) / gridDim.x;
    int r0 = blockIdx.x * rpb;
    int r1 = min(GN, r0 + rpb);
    for (int n0 = r0; n0 < r1; n0 += PT_NB) {
        __syncthreads();
        int n = n0 + w;
        if (n < r1) {
            float2 p = *(const float2*)(g_P + (size_t)n * 64 + lane * 2);
            Ps[w][lane * 2] = p.x;
            Ps[w][lane * 2 + 1] = p.y;
            float2 xe = *(const float2*)(g_XE + (size_t)n * 64 + lane * 2);
            Bsr[w][128 + lane * 2] = xe.x;
            Bsr[w][129 + lane * 2] = xe.y;
            float2 m0v = make_float2(0.f, 0.f);
            float2 m1v = make_float2(0.f, 0.f);
#pragma unroll
            for (int r = 0; r < 2; r++) {
                int beg = g_off[r][n], end = g_off[r][n + 1];
                const int* __restrict__ es = g_esrc[r];
                const float* __restrict__ ea = g_eattr[r];
                for (int k = beg; k < end; k++) {
                    int src = es[k];
                    float a = ea[k];
                    float2 pv = *(const float2*)(g_P + (size_t)src * 64 + lane * 2);
                    if (r == 0) { m0v.x += a * pv.x; m0v.y += a * pv.y; }
                    else        { m1v.x += a * pv.x; m1v.y += a * pv.y; }
                }
            }
            Bsr[w][lane * 2] = m0v.x;
            Bsr[w][lane * 2 + 1] = m0v.y;
            Bsr[w][64 + lane * 2] = m1v.x;
            Bsr[w][65 + lane * 2] = m1v.y;
        } else {
#pragma unroll
            for (int q = 0; q < 2; q++) {
                Ps[w][lane * 2 + q] = 0.f;
                Bsr[w][lane * 2 + q] = 0.f;
                Bsr[w][64 + lane * 2 + q] = 0.f;
                Bsr[w][128 + lane * 2 + q] = 0.f;
            }
        }
        __syncthreads();
#pragma unroll
        for (int j = 0; j < PT_NB; j++) {
            float a[4];
#pragma unroll
            for (int i = 0; i < 4; i++) a[i] = Ps[j][ag * 4 + i];
            float b[12];
#pragma unroll
            for (int q = 0; q < 12; q++) b[q] = Bsr[j][bg * 12 + q];
#pragma unroll
            for (int i = 0; i < 4; i++)
#pragma unroll
                for (int q = 0; q < 12; q++) acc[i][q] += a[i] * b[q];
        }
    }
#pragma unroll
    for (int i = 0; i < 4; i++)
#pragma unroll
        for (int q = 0; q < 12; q++)
            atomicAdd(&g_CO[(ag * 4 + i) * 192 + bg * 12 + q], acc[i][q]);
}

// ---------------- dense 64x64 GNN + head ------------------------------------
#define DSTR 68

template <bool ACC, bool BSMEM>
__device__ __forceinline__ void dmm(float* Cs, const float* As, const float* B,
                                    const float* bias, int tid)
{
    int r0 = (tid >> 4) << 2, c0 = (tid & 15) << 2;
    float acc[4][4];
#pragma unroll
    for (int i = 0; i < 4; i++)
#pragma unroll
        for (int j = 0; j < 4; j++)
            acc[i][j] = ACC ? Cs[(r0 + i) * DSTR + c0 + j] : (bias ? bias[c0 + j] : 0.f);
#pragma unroll 8
    for (int k = 0; k < 64; k++) {
        float a[4];
#pragma unroll
        for (int i = 0; i < 4; i++) a[i] = As[(r0 + i) * DSTR + k];
        float4 bv;
        if (BSMEM) bv = *(const float4*)(B + k * DSTR + c0);
        else bv = *(const float4*)(B + k * 64 + c0);
#pragma unroll
        for (int i = 0; i < 4; i++) {
            acc[i][0] += a[i] * bv.x;
            acc[i][1] += a[i] * bv.y;
            acc[i][2] += a[i] * bv.z;
            acc[i][3] += a[i] * bv.w;
        }
    }
#pragma unroll
    for (int i = 0; i < 4; i++)
#pragma unroll
        for (int j = 0; j < 4; j++)
            Cs[(r0 + i) * DSTR + c0 + j] = acc[i][j];
}

__global__ void dense_final(const float* __restrict__ Wself0, const float* __restrict__ Wrel0,
                            const float* __restrict__ Wself1, const float* __restrict__ Wrel1,
                            const float* __restrict__ gb,
                            const float* __restrict__ lin1W, const float* __restrict__ lin1b,
                            const float* __restrict__ lin2W, const float* __restrict__ lin2b,
                            float* __restrict__ dout, int full)
{
    extern __shared__ float sm[];
    float* X = sm;
    float* A0 = X + 64 * DSTR;
    float* A1 = A0 + 64 * DSTR;
    float* H = A1 + 64 * DSTR;
    float* H2 = H + 64 * DSTR;
    float* T = H2 + 64 * DSTR;
    int tid = threadIdx.x;
    int r0 = (tid >> 4) << 2, c0 = (tid & 15) << 2;
#pragma unroll
    for (int i = 0; i < 4; i++)
#pragma unroll
        for (int j = 0; j < 4; j++) {
            int r = r0 + i, c = c0 + j;
            float xv = g_CO[r * 192 + 128 + c];
            X[r * DSTR + c] = xv;
            if (full) dout[32 + (size_t)GN * 64 + r * 64 + c] = xv;
            A0[r * DSTR + c] = g_CO[r * 192 + c];
            A1[r * DSTR + c] = g_CO[r * 192 + 64 + c];
        }
    __syncthreads();
    dmm<false, false>(H, X, Wself0, gb, tid);          // H = X@Ws0 + b0
    dmm<false, false>(T, X, Wrel0, nullptr, tid);      // T = X@Wr0[0]
    __syncthreads();
    dmm<true, true>(H, A0, T, nullptr, tid);           // H += A0@T
    __syncthreads();
    dmm<false, false>(T, X, Wrel0 + 4096, nullptr, tid);
    __syncthreads();
    dmm<true, true>(H, A1, T, nullptr, tid);
#pragma unroll
    for (int i = 0; i < 4; i++)
#pragma unroll
        for (int j = 0; j < 4; j++) {
            float* p = &H[(r0 + i) * DSTR + c0 + j];
            *p = fmaxf(*p, 0.f);
        }
    __syncthreads();
    dmm<false, false>(H2, H, Wself1, gb + 64, tid);    // H2 = H@Ws1 + b1
    dmm<false, false>(T, H, Wrel1, nullptr, tid);
    __syncthreads();
    dmm<true, true>(H2, A0, T, nullptr, tid);
    __syncthreads();
    dmm<false, false>(T, H, Wrel1 + 4096, nullptr, tid);
    __syncthreads();
    dmm<true, true>(H2, A1, T, nullptr, tid);
#pragma unroll
    for (int i = 0; i < 4; i++)
#pragma unroll
        for (int j = 0; j < 4; j++) {
            float* p = &H2[(r0 + i) * DSTR + c0 + j];
            *p = fmaxf(*p, 0.f);
        }
    __syncthreads();
    if (tid < 64) {
        float s = 0.f;
        for (int r = 0; r < 64; r++) s += H2[r * DSTR + tid];
        T[tid] = s * (1.f / 64.f); // pooled mean over rows
    }
    __syncthreads();
    if (tid < 32) {
        float h1 = lin1b[tid];
        for (int c = 0; c < 64; c++) h1 += T[c] * lin1W[c * 32 + tid];
        h1 = (h1 > 0.f) ? h1 : 0.01f * h1; // leaky_relu
        T[64 + tid] = h1;
        __syncwarp();
        float lg = lin2b[tid];
        for (int j = 0; j < 32; j++) lg += T[64 + j] * lin2W[j * 32 + tid];
        float m = lg;
#pragma unroll
        for (int off = 16; off; off >>= 1) m = fmaxf(m, __shfl_xor_sync(0xffffffffu, m, off));
        float se = expf(lg - m);
#pragma unroll
        for (int off = 16; off; off >>= 1) se += __shfl_xor_sync(0xffffffffu, se, off);
        dout[tid] = lg - m - logf(se);
    }
}

// ---------------- launcher ---------------------------------------------------
extern "C" void kernel_launch(void* const* d_in, const int* in_sizes, int n_in,
                              void* d_out, int out_size)
{
    const float* x = (const float*)d_in[0];
    // resolve edge/attr ordering by sizes (dict order vs signature order)
    int iE0 = 1, iA0 = 2, iE1 = 3, iA1 = 4;
    if (in_sizes[2] == 2 * GE) { iE0 = 1; iE1 = 2; iA0 = 3; iA1 = 4; }
    const int* e0 = (const int*)d_in[iE0];
    const float* a0 = (const float*)d_in[iA0];
    const int* e1 = (const int*)d_in[iE1];
    const float* a1 = (const float*)d_in[iA1];
    const float* W[19];
    for (int i = 0; i < 19; i++) W[i] = (const float*)d_in[5 + i];
    int full = (out_size >= 32 + GN * 64 + 64 * 64) ? 1 : 0;
    float* dout = (float*)d_out;

    cudaFuncSetAttribute(dense_final, cudaFuncAttributeMaxDynamicSharedMemorySize,
                         6 * 64 * DSTR * (int)sizeof(float));

    pack_weights<<<192, 256>>>(W[0], W[1], W[2], W[3], W[4], W[5], W[6], W[7], W[8], W[9]);
    zero_small<<<205, 256>>>();
    hist_kernel<<<2500, 256>>>(e0, e1);
    scan_chunks<<<2 * NCHUNK, 1024>>>();
    scan_fixup<<<2 * NCHUNK, 1024>>>();
    place_kernel<<<2500, 256>>>(e0, a0, e1, a1);
    gemm0_kernel<<<dim3(157, 6), 256>>>(x);
    gather_layer<0><<<2500, 256>>>(dout, full);
    gemm1_kernel<<<dim3(157, 6), 256>>>();
    gather_layer<1><<<2500, 256>>>(dout, full);
    ptgemm_kernel<<<160, 256>>>();
    dense_final<<<1, 256, 6 * 64 * DSTR * sizeof(float)>>>(
        W[10], W[11], W[12], W[13], W[14], W[15], W[16], W[17], W[18], dout, full);
}